// round 1
// baseline (speedup 1.0000x reference)
#include <cuda_runtime.h>

// Problem constants
#define BN 4
#define CN 2048
#define HN 24
#define WN 24
#define LN 576   // H*W

// ---------------- scratch (device globals; no allocation allowed) -----------
__device__ float g_q[(long)BN * 2 * CN * LN];   // [B][2C][L]: rows 0..C-1 = q, rows C..2C-1 = T_part
__device__ float g_k[(long)BN * CN * LN];       // [B][C][L]
__device__ float g_gram[(long)BN * LN * LN];    // [B][L_ref][L_tgt]
__device__ float g_n2[2 * BN * LN];             // pixel squared norms: [which][B][L], which 0=k,1=q
__device__ float g_pn[2 * BN * LN];             // patch norms (clamped): [which][B][L]
__device__ float g_rstar[BN * LN];              // S
__device__ int   g_arg[BN * LN];                // argmax ref index per target pixel
__device__ int   g_idx[BN * LN * 9];            // gather indices for T_part (-1 = zero)

// ---------------- tiled fp32 GEMM ------------------------------------------
// C[M,N] = op(A)[M,K] * B[K,N] (+ epilogue). op(A)=A row-major [M,K] if !TRANSA,
// else A stored [K,M] row-major. B row-major [K,N]. Requires K % 16 == 0,
// N % 4 == 0, M % 4 == 0 (for TRANSA vector loads).
// MODE 0: out = acc + bias[row]
// MODE 1: out = acc
// MODE 2: out = (acc + bias[row]) * Sv[b*LN + col] + resid[b*sR + row*N + col]
template<bool TRANSA, int MODE>
__global__ __launch_bounds__(256)
void gemm_kernel(const float* __restrict__ A, const float* __restrict__ Bm,
                 float* __restrict__ Cm,
                 int M, int N, int K,
                 long sA, long sB, long sC,
                 const float* __restrict__ bias,
                 const float* __restrict__ Sv,
                 const float* __restrict__ resid, long sR)
{
    __shared__ float As[16][128];
    __shared__ float Bs[16][64];

    const int b = blockIdx.z;
    A  += (long)b * sA;
    Bm += (long)b * sB;
    Cm += (long)b * sC;

    const int m0 = blockIdx.y * 128;
    const int n0 = blockIdx.x * 64;
    const int tid = threadIdx.x;
    const int tx = tid & 15;     // n
    const int ty = tid >> 4;     // m

    float acc[8][4];
#pragma unroll
    for (int i = 0; i < 8; i++)
#pragma unroll
        for (int j = 0; j < 4; j++) acc[i][j] = 0.f;

    for (int k0 = 0; k0 < K; k0 += 16) {
        // ---- load A tile into As[kk][m] (transposed in smem) ----
        if (!TRANSA) {
#pragma unroll
            for (int i = 0; i < 2; i++) {
                int idx = tid + i * 256;          // 0..511 float4s
                int m  = idx >> 2;
                int k4 = idx & 3;
                float4 v = make_float4(0.f, 0.f, 0.f, 0.f);
                if (m0 + m < M)
                    v = *(const float4*)(A + (long)(m0 + m) * K + k0 + k4 * 4);
                As[k4 * 4 + 0][m] = v.x;
                As[k4 * 4 + 1][m] = v.y;
                As[k4 * 4 + 2][m] = v.z;
                As[k4 * 4 + 3][m] = v.w;
            }
        } else {
#pragma unroll
            for (int i = 0; i < 2; i++) {
                int idx = tid + i * 256;
                int kk = idx >> 5;                // 0..15
                int m4 = idx & 31;                // 0..31 (×4 floats)
                int mg = m0 + m4 * 4;
                float4 v = make_float4(0.f, 0.f, 0.f, 0.f);
                if (mg < M)
                    v = *(const float4*)(A + (long)(k0 + kk) * M + mg);
                As[kk][m4 * 4 + 0] = v.x;
                As[kk][m4 * 4 + 1] = v.y;
                As[kk][m4 * 4 + 2] = v.z;
                As[kk][m4 * 4 + 3] = v.w;
            }
        }
        // ---- load B tile ----
        {
            int n4 = tid & 15;
            int kk = tid >> 4;
            float4 v = make_float4(0.f, 0.f, 0.f, 0.f);
            if (n0 + n4 * 4 < N)
                v = *(const float4*)(Bm + (long)(k0 + kk) * N + n0 + n4 * 4);
            *(float4*)&Bs[kk][n4 * 4] = v;
        }
        __syncthreads();

#pragma unroll
        for (int kk = 0; kk < 16; kk++) {
            float a[8], bb[4];
#pragma unroll
            for (int i = 0; i < 8; i++) a[i] = As[kk][ty * 8 + i];
#pragma unroll
            for (int j = 0; j < 4; j++) bb[j] = Bs[kk][tx * 4 + j];
#pragma unroll
            for (int i = 0; i < 8; i++)
#pragma unroll
                for (int j = 0; j < 4; j++) acc[i][j] += a[i] * bb[j];
        }
        __syncthreads();
    }

#pragma unroll
    for (int i = 0; i < 8; i++) {
        int row = m0 + ty * 8 + i;
        if (row >= M) continue;
#pragma unroll
        for (int j = 0; j < 4; j++) {
            int col = n0 + tx * 4 + j;
            if (col >= N) continue;
            float v = acc[i][j];
            if (MODE == 0) v += bias[row];
            if (MODE == 2) v = (v + bias[row]) * Sv[b * LN + col]
                              + resid[(long)b * sR + (long)row * N + col];
            Cm[(long)row * N + col] = v;
        }
    }
}

// ---------------- pixel squared norms ---------------------------------------
// grid (LN/32, B, 2), block 256 = 32 l-lanes x 8 c-slices
__global__ void pixnorm_kernel()
{
    const int b = blockIdx.y;
    const int which = blockIdx.z;   // 0 = k, 1 = q
    const int tid = threadIdx.x;
    const int lane = tid & 31;
    const int cs = tid >> 5;
    const int l = blockIdx.x * 32 + lane;
    const float* src = which ? (g_q + (long)b * 2 * CN * LN)
                             : (g_k + (long)b * CN * LN);
    float s = 0.f;
    for (int c = cs; c < CN; c += 8) {
        float v = src[(long)c * LN + l];
        s += v * v;
    }
    __shared__ float red[256];
    red[tid] = s;
    __syncthreads();
    for (int off = 128; off >= 32; off >>= 1) {
        if (tid < off) red[tid] += red[tid + off];
        __syncthreads();
    }
    if (tid < 32) g_n2[which * BN * LN + b * LN + l] = red[tid];
}

// ---------------- patch norms ------------------------------------------------
__global__ void patchnorm_kernel()
{
    int idx = blockIdx.x * blockDim.x + threadIdx.x;
    if (idx >= 2 * BN * LN) return;
    int which = idx / (BN * LN);
    int rem = idx % (BN * LN);
    int b = rem / LN;
    int l = rem % LN;
    int li = l / WN, lj = l % WN;
    const float* n2 = g_n2 + which * BN * LN + b * LN;
    float s = 0.f;
#pragma unroll
    for (int di = -1; di <= 1; di++)
#pragma unroll
        for (int dj = -1; dj <= 1; dj++) {
            int i2 = li + di, j2 = lj + dj;
            if (i2 >= 0 && i2 < HN && j2 >= 0 && j2 < WN)
                s += n2[i2 * WN + j2];
        }
    g_pn[idx] = fmaxf(sqrtf(s), 1e-12f);
}

// ---------------- R + argmax over ref positions ------------------------------
// grid (LN, B), block 128
__global__ void rstar_kernel()
{
    const int m = blockIdx.x;
    const int b = blockIdx.y;
    const int mi = m / WN, mj = m % WN;
    const float* G = g_gram + (long)b * LN * LN;
    const float* pnk = g_pn + b * LN;                 // which=0
    const int tid = threadIdx.x;

    float best = -1e30f;
    int barg = 0;
    for (int l = tid; l < LN; l += 128) {
        int li = l / WN, lj = l % WN;
        float s = 0.f;
#pragma unroll
        for (int di = -1; di <= 1; di++)
#pragma unroll
            for (int dj = -1; dj <= 1; dj++) {
                int li2 = li + di, lj2 = lj + dj;
                int mi2 = mi + di, mj2 = mj + dj;
                if (li2 >= 0 && li2 < HN && lj2 >= 0 && lj2 < WN &&
                    mi2 >= 0 && mi2 < HN && mj2 >= 0 && mj2 < WN) {
                    int off = di * WN + dj;
                    s += G[(long)(l + off) * LN + (m + off)];
                }
            }
        float v = s / pnk[l];
        if (v > best) { best = v; barg = l; }   // strict > keeps first (smallest l)
    }
    __shared__ float sv[128];
    __shared__ int si[128];
    sv[tid] = best; si[tid] = barg;
    __syncthreads();
    for (int off = 64; off >= 1; off >>= 1) {
        if (tid < off) {
            if (sv[tid + off] > sv[tid] ||
                (sv[tid + off] == sv[tid] && si[tid + off] < si[tid])) {
                sv[tid] = sv[tid + off];
                si[tid] = si[tid + off];
            }
        }
        __syncthreads();
    }
    if (tid == 0) {
        g_rstar[b * LN + m] = sv[0] / g_pn[BN * LN + b * LN + m];  // divide by pnq
        g_arg[b * LN + m] = si[0];
    }
}

// ---------------- gather-index precompute (fold o gather o unfold) -----------
__global__ void idx_kernel()
{
    int idx = blockIdx.x * blockDim.x + threadIdx.x;
    if (idx >= BN * LN) return;
    int b = idx / LN;
    int p = idx % LN;
    int pi = p / WN, pj = p % WN;
#pragma unroll
    for (int j = 0; j < 9; j++) {
        int di = j / 3 - 1, dj = j % 3 - 1;
        int mi = pi - di, mj = pj - dj;      // window origin contributing via offset d
        int id = -1;
        if (mi >= 0 && mi < HN && mj >= 0 && mj < WN) {
            int a = g_arg[b * LN + mi * WN + mj];
            int ai = a / WN + di, aj = a % WN + dj;
            if (ai >= 0 && ai < HN && aj >= 0 && aj < WN)
                id = ai * WN + aj;
        }
        g_idx[(long)(b * LN + p) * 9 + j] = id;
    }
}

// ---------------- build T_part into second half of g_q -----------------------
// grid (CN, BN), block LN (=576)
__global__ void tpart_kernel()
{
    const int c = blockIdx.x;
    const int b = blockIdx.y;
    const float* krow = g_k + ((long)b * CN + c) * LN;
    const int* idxr = g_idx + (long)b * LN * 9;
    const int p = threadIdx.x;
    float s = 0.f;
#pragma unroll
    for (int j = 0; j < 9; j++) {
        int id = idxr[p * 9 + j];
        if (id >= 0) s += krow[id];
    }
    g_q[((long)b * 2 * CN + CN + c) * LN + p] = s * (1.f / 9.f);
}

// ---------------- host launch ------------------------------------------------
extern "C" void kernel_launch(void* const* d_in, const int* in_sizes, int n_in,
                              void* d_out, int out_size)
{
    const float* part_ref    = (const float*)d_in[0];
    const float* part_target = (const float*)d_in[1];
    const float* wq = (const float*)d_in[2];
    const float* bq = (const float*)d_in[3];
    const float* wk = (const float*)d_in[4];
    const float* bk = (const float*)d_in[5];
    const float* wt = (const float*)d_in[6];
    const float* bt = (const float*)d_in[7];
    float* out = (float*)d_out;

    float* q_ptr;  cudaGetSymbolAddress((void**)&q_ptr,  g_q);
    float* k_ptr;  cudaGetSymbolAddress((void**)&k_ptr,  g_k);
    float* g_ptr;  cudaGetSymbolAddress((void**)&g_ptr,  g_gram);
    float* s_ptr;  cudaGetSymbolAddress((void**)&s_ptr,  g_rstar);

    dim3 blk(256);

    // 1) q = wq @ part_target + bq   -> g_q rows [0,C)
    {
        dim3 grid(LN / 64, CN / 128, BN);
        gemm_kernel<false, 0><<<grid, blk>>>(wq, part_target, q_ptr,
            CN, LN, CN, 0L, (long)CN * LN, (long)2 * CN * LN,
            bq, nullptr, nullptr, 0L);
    }
    // 2) k = wk @ part_ref + bk      -> g_k
    {
        dim3 grid(LN / 64, CN / 128, BN);
        gemm_kernel<false, 0><<<grid, blk>>>(wk, part_ref, k_ptr,
            CN, LN, CN, 0L, (long)CN * LN, (long)CN * LN,
            bk, nullptr, nullptr, 0L);
    }
    // 3) pixel squared norms (k and q)
    pixnorm_kernel<<<dim3(LN / 32, BN, 2), 256>>>();
    // 4) patch norms
    patchnorm_kernel<<<(2 * BN * LN + 255) / 256, 256>>>();
    // 5) Gram: G[l,m] = sum_c k[c,l] q[c,m]
    {
        dim3 grid(LN / 64, (LN + 127) / 128, BN);
        gemm_kernel<true, 1><<<grid, blk>>>(k_ptr, q_ptr, g_ptr,
            LN, LN, CN, (long)CN * LN, (long)2 * CN * LN, (long)LN * LN,
            nullptr, nullptr, nullptr, 0L);
    }
    // 6) R_star + argmax
    rstar_kernel<<<dim3(LN, BN), 128>>>();
    // 7) gather indices
    idx_kernel<<<(BN * LN + 255) / 256, 256>>>();
    // 8) T_part -> g_q rows [C,2C)
    tpart_kernel<<<dim3(CN, BN), LN>>>();
    // 9) final: out = (wt @ [q;T_part] + bt) * S + part_target
    {
        dim3 grid(LN / 64, CN / 128, BN);
        gemm_kernel<false, 2><<<grid, blk>>>(wt, q_ptr, out,
            CN, LN, 2 * CN, 0L, (long)2 * CN * LN, (long)CN * LN,
            bt, s_ptr, part_target, (long)CN * LN);
    }
}

// round 3
// speedup vs baseline: 1.0001x; 1.0001x over previous
#include <cuda_runtime.h>

// Problem constants
#define BN 4
#define CN 2048
#define HN 24
#define WN 24
#define LN 576   // H*W

// ---------------- scratch (device globals; no allocation allowed) -----------
__device__ float g_q[(long)BN * 2 * CN * LN];   // [B][2C][L]: rows 0..C-1 = q, rows C..2C-1 = T_part
__device__ float g_k[(long)BN * CN * LN];       // [B][C][L]
__device__ float g_gram[(long)BN * LN * LN];    // [B][L_ref][L_tgt]
__device__ float g_n2[2 * BN * LN];             // pixel squared norms: [which][B][L], which 0=k,1=q
__device__ float g_pn[2 * BN * LN];             // patch norms (clamped): [which][B][L]
__device__ float g_rstar[BN * LN];              // S
__device__ int   g_arg[BN * LN];                // argmax ref index per target pixel
__device__ int   g_idx[BN * LN * 9];            // gather indices for T_part (-1 = zero)

// ---------------- tiled fp32 GEMM ------------------------------------------
// C[M,N] = op(A)[M,K] * B[K,N] (+ epilogue). op(A)=A row-major [M,K] if !TRANSA,
// else A stored [K,M] row-major. B row-major [K,N]. Requires K % 16 == 0,
// N % 4 == 0, M % 4 == 0 (for TRANSA vector loads).
// MODE 0: out = acc + bias[row]
// MODE 1: out = acc
// MODE 2: out = (acc + bias[row]) * Sv[b*LN + col] + resid[b*sR + row*N + col]
template<bool TRANSA, int MODE>
__global__ __launch_bounds__(256)
void gemm_kernel(const float* __restrict__ A, const float* __restrict__ Bm,
                 float* __restrict__ Cm,
                 int M, int N, int K,
                 long sA, long sB, long sC,
                 const float* __restrict__ bias,
                 const float* __restrict__ Sv,
                 const float* __restrict__ resid, long sR)
{
    __shared__ float As[16][128];
    __shared__ float Bs[16][64];

    const int b = blockIdx.z;
    A  += (long)b * sA;
    Bm += (long)b * sB;
    Cm += (long)b * sC;

    const int m0 = blockIdx.y * 128;
    const int n0 = blockIdx.x * 64;
    const int tid = threadIdx.x;
    const int tx = tid & 15;     // n
    const int ty = tid >> 4;     // m

    float acc[8][4];
#pragma unroll
    for (int i = 0; i < 8; i++)
#pragma unroll
        for (int j = 0; j < 4; j++) acc[i][j] = 0.f;

    for (int k0 = 0; k0 < K; k0 += 16) {
        // ---- load A tile into As[kk][m] (transposed in smem) ----
        if (!TRANSA) {
#pragma unroll
            for (int i = 0; i < 2; i++) {
                int idx = tid + i * 256;          // 0..511 float4s
                int m  = idx >> 2;
                int k4 = idx & 3;
                float4 v = make_float4(0.f, 0.f, 0.f, 0.f);
                if (m0 + m < M)
                    v = *(const float4*)(A + (long)(m0 + m) * K + k0 + k4 * 4);
                As[k4 * 4 + 0][m] = v.x;
                As[k4 * 4 + 1][m] = v.y;
                As[k4 * 4 + 2][m] = v.z;
                As[k4 * 4 + 3][m] = v.w;
            }
        } else {
#pragma unroll
            for (int i = 0; i < 2; i++) {
                int idx = tid + i * 256;
                int kk = idx >> 5;                // 0..15
                int m4 = idx & 31;                // 0..31 (×4 floats)
                int mg = m0 + m4 * 4;
                float4 v = make_float4(0.f, 0.f, 0.f, 0.f);
                if (mg < M)
                    v = *(const float4*)(A + (long)(k0 + kk) * M + mg);
                As[kk][m4 * 4 + 0] = v.x;
                As[kk][m4 * 4 + 1] = v.y;
                As[kk][m4 * 4 + 2] = v.z;
                As[kk][m4 * 4 + 3] = v.w;
            }
        }
        // ---- load B tile ----
        {
            int n4 = tid & 15;
            int kk = tid >> 4;
            float4 v = make_float4(0.f, 0.f, 0.f, 0.f);
            if (n0 + n4 * 4 < N)
                v = *(const float4*)(Bm + (long)(k0 + kk) * N + n0 + n4 * 4);
            *(float4*)&Bs[kk][n4 * 4] = v;
        }
        __syncthreads();

#pragma unroll
        for (int kk = 0; kk < 16; kk++) {
            float a[8], bb[4];
#pragma unroll
            for (int i = 0; i < 8; i++) a[i] = As[kk][ty * 8 + i];
#pragma unroll
            for (int j = 0; j < 4; j++) bb[j] = Bs[kk][tx * 4 + j];
#pragma unroll
            for (int i = 0; i < 8; i++)
#pragma unroll
                for (int j = 0; j < 4; j++) acc[i][j] += a[i] * bb[j];
        }
        __syncthreads();
    }

#pragma unroll
    for (int i = 0; i < 8; i++) {
        int row = m0 + ty * 8 + i;
        if (row >= M) continue;
#pragma unroll
        for (int j = 0; j < 4; j++) {
            int col = n0 + tx * 4 + j;
            if (col >= N) continue;
            float v = acc[i][j];
            if (MODE == 0) v += bias[row];
            if (MODE == 2) v = (v + bias[row]) * Sv[b * LN + col]
                              + resid[(long)b * sR + (long)row * N + col];
            Cm[(long)row * N + col] = v;
        }
    }
}

// ---------------- pixel squared norms ---------------------------------------
// grid (LN/32, B, 2), block 256 = 32 l-lanes x 8 c-slices
__global__ void pixnorm_kernel()
{
    const int b = blockIdx.y;
    const int which = blockIdx.z;   // 0 = k, 1 = q
    const int tid = threadIdx.x;
    const int lane = tid & 31;
    const int cs = tid >> 5;
    const int l = blockIdx.x * 32 + lane;
    const float* src = which ? (g_q + (long)b * 2 * CN * LN)
                             : (g_k + (long)b * CN * LN);
    float s = 0.f;
    for (int c = cs; c < CN; c += 8) {
        float v = src[(long)c * LN + l];
        s += v * v;
    }
    __shared__ float red[256];
    red[tid] = s;
    __syncthreads();
    for (int off = 128; off >= 32; off >>= 1) {
        if (tid < off) red[tid] += red[tid + off];
        __syncthreads();
    }
    if (tid < 32) g_n2[which * BN * LN + b * LN + l] = red[tid];
}

// ---------------- patch norms ------------------------------------------------
__global__ void patchnorm_kernel()
{
    int idx = blockIdx.x * blockDim.x + threadIdx.x;
    if (idx >= 2 * BN * LN) return;
    int which = idx / (BN * LN);
    int rem = idx % (BN * LN);
    int b = rem / LN;
    int l = rem % LN;
    int li = l / WN, lj = l % WN;
    const float* n2 = g_n2 + which * BN * LN + b * LN;
    float s = 0.f;
#pragma unroll
    for (int di = -1; di <= 1; di++)
#pragma unroll
        for (int dj = -1; dj <= 1; dj++) {
            int i2 = li + di, j2 = lj + dj;
            if (i2 >= 0 && i2 < HN && j2 >= 0 && j2 < WN)
                s += n2[i2 * WN + j2];
        }
    g_pn[idx] = fmaxf(sqrtf(s), 1e-12f);
}

// ---------------- R + argmax over ref positions ------------------------------
// grid (LN, B), block 128
__global__ void rstar_kernel()
{
    const int m = blockIdx.x;
    const int b = blockIdx.y;
    const int mi = m / WN, mj = m % WN;
    const float* G = g_gram + (long)b * LN * LN;
    const float* pnk = g_pn + b * LN;                 // which=0
    const int tid = threadIdx.x;

    float best = -1e30f;
    int barg = 0;
    for (int l = tid; l < LN; l += 128) {
        int li = l / WN, lj = l % WN;
        float s = 0.f;
#pragma unroll
        for (int di = -1; di <= 1; di++)
#pragma unroll
            for (int dj = -1; dj <= 1; dj++) {
                int li2 = li + di, lj2 = lj + dj;
                int mi2 = mi + di, mj2 = mj + dj;
                if (li2 >= 0 && li2 < HN && lj2 >= 0 && lj2 < WN &&
                    mi2 >= 0 && mi2 < HN && mj2 >= 0 && mj2 < WN) {
                    int off = di * WN + dj;
                    s += G[(long)(l + off) * LN + (m + off)];
                }
            }
        float v = s / pnk[l];
        if (v > best) { best = v; barg = l; }   // strict > keeps first (smallest l)
    }
    __shared__ float sv[128];
    __shared__ int si[128];
    sv[tid] = best; si[tid] = barg;
    __syncthreads();
    for (int off = 64; off >= 1; off >>= 1) {
        if (tid < off) {
            if (sv[tid + off] > sv[tid] ||
                (sv[tid + off] == sv[tid] && si[tid + off] < si[tid])) {
                sv[tid] = sv[tid + off];
                si[tid] = si[tid + off];
            }
        }
        __syncthreads();
    }
    if (tid == 0) {
        g_rstar[b * LN + m] = sv[0] / g_pn[BN * LN + b * LN + m];  // divide by pnq
        g_arg[b * LN + m] = si[0];
    }
}

// ---------------- gather-index precompute (fold o gather o unfold) -----------
__global__ void idx_kernel()
{
    int idx = blockIdx.x * blockDim.x + threadIdx.x;
    if (idx >= BN * LN) return;
    int b = idx / LN;
    int p = idx % LN;
    int pi = p / WN, pj = p % WN;
#pragma unroll
    for (int j = 0; j < 9; j++) {
        int di = j / 3 - 1, dj = j % 3 - 1;
        int mi = pi - di, mj = pj - dj;      // window origin contributing via offset d
        int id = -1;
        if (mi >= 0 && mi < HN && mj >= 0 && mj < WN) {
            int a = g_arg[b * LN + mi * WN + mj];
            int ai = a / WN + di, aj = a % WN + dj;
            if (ai >= 0 && ai < HN && aj >= 0 && aj < WN)
                id = ai * WN + aj;
        }
        g_idx[(long)(b * LN + p) * 9 + j] = id;
    }
}

// ---------------- build T_part into second half of g_q -----------------------
// grid (CN, BN), block LN (=576)
__global__ void tpart_kernel()
{
    const int c = blockIdx.x;
    const int b = blockIdx.y;
    const float* krow = g_k + ((long)b * CN + c) * LN;
    const int* idxr = g_idx + (long)b * LN * 9;
    const int p = threadIdx.x;
    float s = 0.f;
#pragma unroll
    for (int j = 0; j < 9; j++) {
        int id = idxr[p * 9 + j];
        if (id >= 0) s += krow[id];
    }
    g_q[((long)b * 2 * CN + CN + c) * LN + p] = s * (1.f / 9.f);
}

// ---------------- host launch ------------------------------------------------
extern "C" void kernel_launch(void* const* d_in, const int* in_sizes, int n_in,
                              void* d_out, int out_size)
{
    const float* part_ref    = (const float*)d_in[0];
    const float* part_target = (const float*)d_in[1];
    const float* wq = (const float*)d_in[2];
    const float* bq = (const float*)d_in[3];
    const float* wk = (const float*)d_in[4];
    const float* bk = (const float*)d_in[5];
    const float* wt = (const float*)d_in[6];
    const float* bt = (const float*)d_in[7];
    float* out = (float*)d_out;

    float* q_ptr;  cudaGetSymbolAddress((void**)&q_ptr,  g_q);
    float* k_ptr;  cudaGetSymbolAddress((void**)&k_ptr,  g_k);
    float* g_ptr;  cudaGetSymbolAddress((void**)&g_ptr,  g_gram);
    float* s_ptr;  cudaGetSymbolAddress((void**)&s_ptr,  g_rstar);

    dim3 blk(256);

    // 1) q = wq @ part_target + bq   -> g_q rows [0,C)
    {
        dim3 grid(LN / 64, CN / 128, BN);
        gemm_kernel<false, 0><<<grid, blk>>>(wq, part_target, q_ptr,
            CN, LN, CN, 0L, (long)CN * LN, (long)2 * CN * LN,
            bq, nullptr, nullptr, 0L);
    }
    // 2) k = wk @ part_ref + bk      -> g_k
    {
        dim3 grid(LN / 64, CN / 128, BN);
        gemm_kernel<false, 0><<<grid, blk>>>(wk, part_ref, k_ptr,
            CN, LN, CN, 0L, (long)CN * LN, (long)CN * LN,
            bk, nullptr, nullptr, 0L);
    }
    // 3) pixel squared norms (k and q)
    pixnorm_kernel<<<dim3(LN / 32, BN, 2), 256>>>();
    // 4) patch norms
    patchnorm_kernel<<<(2 * BN * LN + 255) / 256, 256>>>();
    // 5) Gram: G[l,m] = sum_c k[c,l] q[c,m]
    {
        dim3 grid(LN / 64, (LN + 127) / 128, BN);
        gemm_kernel<true, 1><<<grid, blk>>>(k_ptr, q_ptr, g_ptr,
            LN, LN, CN, (long)CN * LN, (long)2 * CN * LN, (long)LN * LN,
            nullptr, nullptr, nullptr, 0L);
    }
    // 6) R_star + argmax
    rstar_kernel<<<dim3(LN, BN), 128>>>();
    // 7) gather indices
    idx_kernel<<<(BN * LN + 255) / 256, 256>>>();
    // 8) T_part -> g_q rows [C,2C)
    tpart_kernel<<<dim3(CN, BN), LN>>>();
    // 9) final: out = (wt @ [q;T_part] + bt) * S + part_target
    {
        dim3 grid(LN / 64, CN / 128, BN);
        gemm_kernel<false, 2><<<grid, blk>>>(wt, q_ptr, out,
            CN, LN, 2 * CN, 0L, (long)2 * CN * LN, (long)CN * LN,
            bt, s_ptr, part_target, (long)CN * LN);
    }
}

// round 4
// speedup vs baseline: 2.8217x; 2.8214x over previous
#include <cuda_runtime.h>

// Problem constants
#define BN 4
#define CN 2048
#define HN 24
#define WN 24
#define LN 576   // H*W

// GEMM tile constants
#define TBM 128
#define TBN 64
#define TBK 32
#define APADT (TBM + 8)   // TRANSA smem row stride (k-major)
#define APADN (TBK + 4)   // normal smem row stride (m-major)
#define BPAD  (TBN + 8)

// ---------------- scratch (device globals; no allocation allowed) -----------
__device__ float g_q[(long)BN * 2 * CN * LN];   // [B][2C][L]: rows 0..C-1 = q, rows C..2C-1 = T_part
__device__ float g_k[(long)BN * CN * LN];       // [B][C][L]
__device__ float g_gram[(long)BN * LN * LN];    // [B][L_ref][L_tgt]
__device__ float g_n2[2 * BN * LN];
__device__ float g_pn[2 * BN * LN];
__device__ float g_rstar[BN * LN];
__device__ int   g_arg[BN * LN];
__device__ int   g_idx[BN * LN * 9];

__device__ __forceinline__ unsigned su(const void* p) {
    return (unsigned)__cvta_generic_to_shared(p);
}
#define CP16(d, s, sz) \
    asm volatile("cp.async.cg.shared.global [%0], [%1], 16, %2;" \
                 :: "r"(d), "l"(s), "r"(sz))

// ---------------- tf32 tensor-core GEMM -------------------------------------
// C[M,N] = op(A)[M,K] * B[K,N]. op(A)=A row-major [M,K] if !TRANSA, else A
// stored [K,M] row-major. B row-major [K,N]. K%32==0, N%TBN==0.
// MODE 0: out = acc + bias[row]
// MODE 1: out = acc
// MODE 2: out = (acc + bias[row]) * Sv[b*LN+col] + resid[b*sR + row*N + col]
template<bool TRANSA, int MODE>
__global__ __launch_bounds__(256)
void gemm_tc(const float* __restrict__ A, const float* __restrict__ Bm,
             float* __restrict__ Cm, int M, int N, int K,
             long sA, long sB, long sC,
             const float* __restrict__ bias,
             const float* __restrict__ Sv,
             const float* __restrict__ resid, long sR)
{
    extern __shared__ float smem[];
    const int ASZ = TRANSA ? TBK * APADT : TBM * APADN;
    const int BSZ = TBK * BPAD;
    const int BUF = ASZ + BSZ;

    const int b = blockIdx.z;
    A  += (long)b * sA;
    Bm += (long)b * sB;
    Cm += (long)b * sC;

    const int m0 = blockIdx.y * TBM;
    const int n0 = blockIdx.x * TBN;
    const int t  = threadIdx.x;
    const int lane = t & 31;
    const int w = t >> 5;
    const int wm = (w >> 1) * 32;
    const int wn = (w & 1) * 32;
    const int gid = lane >> 2;
    const int tig = lane & 3;

    float acc[2][4][4];
#pragma unroll
    for (int mt = 0; mt < 2; mt++)
#pragma unroll
        for (int nt = 0; nt < 4; nt++)
#pragma unroll
            for (int r = 0; r < 4; r++) acc[mt][nt][r] = 0.f;

    auto stage = [&](int k0, int buf) {
        float* as = smem + buf * BUF;
        float* bs = as + ASZ;
        if (!TRANSA) {
#pragma unroll
            for (int i = 0; i < 4; i++) {
                int idx = t + i * 256;
                int m = idx >> 3, k4 = idx & 7;
                const float* src = A + (long)(m0 + m) * K + k0 + k4 * 4;
                CP16(su(as + m * APADN + k4 * 4), src, 16);
            }
        } else {
#pragma unroll
            for (int i = 0; i < 4; i++) {
                int idx = t + i * 256;
                int kk = idx >> 5, m4 = idx & 31;
                const float* src = A + (long)(k0 + kk) * M + m0 + m4 * 4;
                int ok = (m0 + m4 * 4 < M) ? 16 : 0;
                CP16(su(as + kk * APADT + m4 * 4), src, ok);
            }
        }
#pragma unroll
        for (int i = 0; i < 2; i++) {
            int idx = t + i * 256;
            int kk = idx >> 4, n4 = idx & 15;
            const float* src = Bm + (long)(k0 + kk) * N + n0 + n4 * 4;
            CP16(su(bs + kk * BPAD + n4 * 4), src, 16);
        }
        asm volatile("cp.async.commit_group;");
    };

    const int niter = K / TBK;
    stage(0, 0);

    for (int it = 0; it < niter; it++) {
        asm volatile("cp.async.wait_group 0;");
        __syncthreads();
        if (it + 1 < niter) stage((it + 1) * TBK, (it + 1) & 1);

        const float* as = smem + (it & 1) * BUF;
        const float* bs = as + ASZ;

#pragma unroll
        for (int ks = 0; ks < TBK / 8; ks++) {
            const int k = ks * 8;
            unsigned af[2][4], bf[4][2];
#pragma unroll
            for (int mt = 0; mt < 2; mt++) {
                int mrow = wm + mt * 16 + gid;
#pragma unroll
                for (int r = 0; r < 4; r++) {
                    int mr = mrow + (r & 1) * 8;
                    int kc = k + tig + (r >> 1) * 4;
                    float v = TRANSA ? as[kc * APADT + mr]
                                     : as[mr * APADN + kc];
                    asm("cvt.rna.tf32.f32 %0, %1;" : "=r"(af[mt][r]) : "f"(v));
                }
            }
#pragma unroll
            for (int nt = 0; nt < 4; nt++) {
                int nc = wn + nt * 8 + gid;
#pragma unroll
                for (int r = 0; r < 2; r++) {
                    float v = bs[(k + tig + r * 4) * BPAD + nc];
                    asm("cvt.rna.tf32.f32 %0, %1;" : "=r"(bf[nt][r]) : "f"(v));
                }
            }
#pragma unroll
            for (int mt = 0; mt < 2; mt++)
#pragma unroll
                for (int nt = 0; nt < 4; nt++)
                    asm volatile(
                        "mma.sync.aligned.m16n8k8.row.col.f32.tf32.tf32.f32 "
                        "{%0,%1,%2,%3},{%4,%5,%6,%7},{%8,%9},{%0,%1,%2,%3};"
                        : "+f"(acc[mt][nt][0]), "+f"(acc[mt][nt][1]),
                          "+f"(acc[mt][nt][2]), "+f"(acc[mt][nt][3])
                        : "r"(af[mt][0]), "r"(af[mt][1]),
                          "r"(af[mt][2]), "r"(af[mt][3]),
                          "r"(bf[nt][0]), "r"(bf[nt][1]));
        }
        __syncthreads();
    }

    // ---- epilogue ----
#pragma unroll
    for (int mt = 0; mt < 2; mt++) {
#pragma unroll
        for (int nt = 0; nt < 4; nt++) {
#pragma unroll
            for (int r = 0; r < 4; r++) {
                int row = m0 + wm + mt * 16 + gid + (r >> 1) * 8;
                int col = n0 + wn + nt * 8 + tig * 2 + (r & 1);
                if (row < M) {
                    float v = acc[mt][nt][r];
                    if (MODE == 0) v += bias[row];
                    if (MODE == 2)
                        v = (v + bias[row]) * Sv[b * LN + col]
                            + resid[(long)b * sR + (long)row * N + col];
                    Cm[(long)row * N + col] = v;
                }
            }
        }
    }
}

// ---------------- pixel squared norms ---------------------------------------
__global__ void pixnorm_kernel()
{
    const int b = blockIdx.y;
    const int which = blockIdx.z;
    const int tid = threadIdx.x;
    const int lane = tid & 31;
    const int cs = tid >> 5;
    const int l = blockIdx.x * 32 + lane;
    const float* src = which ? (g_q + (long)b * 2 * CN * LN)
                             : (g_k + (long)b * CN * LN);
    float s = 0.f;
    for (int c = cs; c < CN; c += 8) {
        float v = src[(long)c * LN + l];
        s += v * v;
    }
    __shared__ float red[256];
    red[tid] = s;
    __syncthreads();
    for (int off = 128; off >= 32; off >>= 1) {
        if (tid < off) red[tid] += red[tid + off];
        __syncthreads();
    }
    if (tid < 32) g_n2[which * BN * LN + b * LN + l] = red[tid];
}

// ---------------- patch norms ------------------------------------------------
__global__ void patchnorm_kernel()
{
    int idx = blockIdx.x * blockDim.x + threadIdx.x;
    if (idx >= 2 * BN * LN) return;
    int which = idx / (BN * LN);
    int rem = idx % (BN * LN);
    int b = rem / LN;
    int l = rem % LN;
    int li = l / WN, lj = l % WN;
    const float* n2 = g_n2 + which * BN * LN + b * LN;
    float s = 0.f;
#pragma unroll
    for (int di = -1; di <= 1; di++)
#pragma unroll
        for (int dj = -1; dj <= 1; dj++) {
            int i2 = li + di, j2 = lj + dj;
            if (i2 >= 0 && i2 < HN && j2 >= 0 && j2 < WN)
                s += n2[i2 * WN + j2];
        }
    g_pn[idx] = fmaxf(sqrtf(s), 1e-12f);
}

// ---------------- R + argmax over ref positions ------------------------------
__global__ void rstar_kernel()
{
    const int m = blockIdx.x;
    const int b = blockIdx.y;
    const int mi = m / WN, mj = m % WN;
    const float* G = g_gram + (long)b * LN * LN;
    const float* pnk = g_pn + b * LN;
    const int tid = threadIdx.x;

    float best = -1e30f;
    int barg = 0;
    for (int l = tid; l < LN; l += 128) {
        int li = l / WN, lj = l % WN;
        float s = 0.f;
#pragma unroll
        for (int di = -1; di <= 1; di++)
#pragma unroll
            for (int dj = -1; dj <= 1; dj++) {
                int li2 = li + di, lj2 = lj + dj;
                int mi2 = mi + di, mj2 = mj + dj;
                if (li2 >= 0 && li2 < HN && lj2 >= 0 && lj2 < WN &&
                    mi2 >= 0 && mi2 < HN && mj2 >= 0 && mj2 < WN) {
                    int off = di * WN + dj;
                    s += G[(long)(l + off) * LN + (m + off)];
                }
            }
        float v = s / pnk[l];
        if (v > best) { best = v; barg = l; }
    }
    __shared__ float sv[128];
    __shared__ int si[128];
    sv[tid] = best; si[tid] = barg;
    __syncthreads();
    for (int off = 64; off >= 1; off >>= 1) {
        if (tid < off) {
            if (sv[tid + off] > sv[tid] ||
                (sv[tid + off] == sv[tid] && si[tid + off] < si[tid])) {
                sv[tid] = sv[tid + off];
                si[tid] = si[tid + off];
            }
        }
        __syncthreads();
    }
    if (tid == 0) {
        g_rstar[b * LN + m] = sv[0] / g_pn[BN * LN + b * LN + m];
        g_arg[b * LN + m] = si[0];
    }
}

// ---------------- gather-index precompute ------------------------------------
__global__ void idx_kernel()
{
    int idx = blockIdx.x * blockDim.x + threadIdx.x;
    if (idx >= BN * LN) return;
    int b = idx / LN;
    int p = idx % LN;
    int pi = p / WN, pj = p % WN;
#pragma unroll
    for (int j = 0; j < 9; j++) {
        int di = j / 3 - 1, dj = j % 3 - 1;
        int mi = pi - di, mj = pj - dj;
        int id = -1;
        if (mi >= 0 && mi < HN && mj >= 0 && mj < WN) {
            int a = g_arg[b * LN + mi * WN + mj];
            int ai = a / WN + di, aj = a % WN + dj;
            if (ai >= 0 && ai < HN && aj >= 0 && aj < WN)
                id = ai * WN + aj;
        }
        g_idx[(long)(b * LN + p) * 9 + j] = id;
    }
}

// ---------------- build T_part into second half of g_q -----------------------
__global__ void tpart_kernel()
{
    const int c = blockIdx.x;
    const int b = blockIdx.y;
    const float* krow = g_k + ((long)b * CN + c) * LN;
    const int* idxr = g_idx + (long)b * LN * 9;
    const int p = threadIdx.x;
    float s = 0.f;
#pragma unroll
    for (int j = 0; j < 9; j++) {
        int id = idxr[p * 9 + j];
        if (id >= 0) s += krow[id];
    }
    g_q[((long)b * 2 * CN + CN + c) * LN + p] = s * (1.f / 9.f);
}

// ---------------- host launch ------------------------------------------------
extern "C" void kernel_launch(void* const* d_in, const int* in_sizes, int n_in,
                              void* d_out, int out_size)
{
    const float* part_ref    = (const float*)d_in[0];
    const float* part_target = (const float*)d_in[1];
    const float* wq = (const float*)d_in[2];
    const float* bq = (const float*)d_in[3];
    const float* wk = (const float*)d_in[4];
    const float* bk = (const float*)d_in[5];
    const float* wt = (const float*)d_in[6];
    const float* bt = (const float*)d_in[7];
    float* out = (float*)d_out;

    float* q_ptr;  cudaGetSymbolAddress((void**)&q_ptr,  g_q);
    float* k_ptr;  cudaGetSymbolAddress((void**)&k_ptr,  g_k);
    float* g_ptr;  cudaGetSymbolAddress((void**)&g_ptr,  g_gram);
    float* s_ptr;  cudaGetSymbolAddress((void**)&s_ptr,  g_rstar);

    // dynamic smem sizes (double-buffered)
    const int smemN = 2 * (TBM * APADN + TBK * BPAD) * 4;  // !TRANSA: 55296 B
    const int smemT = 2 * (TBK * APADT + TBK * BPAD) * 4;  // TRANSA:  53248 B
    cudaFuncSetAttribute(gemm_tc<false, 0>,
        cudaFuncAttributeMaxDynamicSharedMemorySize, smemN);
    cudaFuncSetAttribute(gemm_tc<true, 1>,
        cudaFuncAttributeMaxDynamicSharedMemorySize, smemT);
    cudaFuncSetAttribute(gemm_tc<false, 2>,
        cudaFuncAttributeMaxDynamicSharedMemorySize, smemN);

    dim3 blk(256);

    // 1) q = wq @ part_target + bq   -> g_q rows [0,C)
    gemm_tc<false, 0><<<dim3(LN / TBN, CN / TBM, BN), blk, smemN>>>(
        wq, part_target, q_ptr, CN, LN, CN,
        0L, (long)CN * LN, (long)2 * CN * LN, bq, nullptr, nullptr, 0L);

    // 2) k = wk @ part_ref + bk      -> g_k
    gemm_tc<false, 0><<<dim3(LN / TBN, CN / TBM, BN), blk, smemN>>>(
        wk, part_ref, k_ptr, CN, LN, CN,
        0L, (long)CN * LN, (long)CN * LN, bk, nullptr, nullptr, 0L);

    // 3) pixel squared norms
    pixnorm_kernel<<<dim3(LN / 32, BN, 2), 256>>>();
    // 4) patch norms
    patchnorm_kernel<<<(2 * BN * LN + 255) / 256, 256>>>();

    // 5) Gram: G[l,m] = sum_c k[c,l] q[c,m]
    gemm_tc<true, 1><<<dim3(LN / TBN, (LN + TBM - 1) / TBM, BN), blk, smemT>>>(
        k_ptr, q_ptr, g_ptr, LN, LN, CN,
        (long)CN * LN, (long)2 * CN * LN, (long)LN * LN,
        nullptr, nullptr, nullptr, 0L);

    // 6) R_star + argmax
    rstar_kernel<<<dim3(LN, BN), 128>>>();
    // 7) gather indices
    idx_kernel<<<(BN * LN + 255) / 256, 256>>>();
    // 8) T_part -> g_q rows [C,2C)
    tpart_kernel<<<dim3(CN, BN), LN>>>();

    // 9) final: out = (wt @ [q;T_part] + bt) * S + part_target
    gemm_tc<false, 2><<<dim3(LN / TBN, CN / TBM, BN), blk, smemN>>>(
        wt, q_ptr, out, CN, LN, 2 * CN,
        0L, (long)2 * CN * LN, (long)CN * LN, bt, s_ptr, part_target,
        (long)CN * LN);
}

// round 7
// speedup vs baseline: 2.9344x; 1.0399x over previous
#include <cuda_runtime.h>
#include <cstdint>

// Problem constants
#define BN 4
#define CN 2048
#define HN 24
#define WN 24
#define LN 576   // H*W

// GEMM tile constants
#define TBM 128
#define TBN 128
#define TBK 32
#define APADN 36    // !TRANSA A smem row stride (m-major, k contiguous-ish)
#define APADT 136   // TRANSA  A smem row stride (k-major)
#define BPAD  136

// ---------------- scratch (device globals; no allocation allowed) -----------
__device__ float g_q[(long)BN * 2 * CN * LN];   // [B][2C][L]: rows 0..C-1 = q, C..2C-1 = T_part (tf32-rounded)
__device__ float g_k[(long)BN * CN * LN];       // [B][C][L] (tf32-rounded)
__device__ float g_pt[(long)BN * CN * LN];      // part_target rounded
__device__ float g_pr[(long)BN * CN * LN];      // part_ref rounded
__device__ float g_wq[(long)CN * CN];
__device__ float g_wk[(long)CN * CN];
__device__ float g_wt[(long)CN * 2 * CN];
__device__ float g_gram[(long)BN * LN * LN];    // [B][L_ref][L_tgt]
__device__ float g_n2[2 * BN * LN];
__device__ float g_pn[2 * BN * LN];
__device__ float g_rstar[BN * LN];
__device__ int   g_arg[BN * LN];
__device__ int   g_idx[BN * LN * 9];

__device__ __forceinline__ unsigned su(const void* p) {
    return (unsigned)__cvta_generic_to_shared(p);
}
#define CP16(d, s, sz) \
    asm volatile("cp.async.cg.shared.global [%0], [%1], 16, %2;" \
                 :: "r"(d), "l"(s), "r"(sz))

__device__ __forceinline__ float rna_tf32(float v) {
    uint32_t u;
    asm("cvt.rna.tf32.f32 %0, %1;" : "=r"(u) : "f"(v));
    return __uint_as_float(u);
}

// ---------------- tf32 tensor-core GEMM (mma.sync, pre-rounded operands) ----
// C[M, LN] = op(A)[M,K] * B[K,LN]. op(A)=A row-major [M,K] if !TRANSA, else A
// stored [K,M] row-major. B row-major [K,LN]. All A/B values MUST already be
// tf32-rounded. K % 32 == 0.
// MODE 0: out = rna(acc + bias[row])
// MODE 1: out = acc
// MODE 2: out = (acc + bias[row]) * Sv[b*LN+col] + resid[b*sR + row*LN + col]
template<bool TRANSA, int MODE>
__global__ __launch_bounds__(256)
void gemm_tc(const float* __restrict__ A, const float* __restrict__ Bm,
             float* __restrict__ Cm, int M, int K,
             long sA, long sB, long sC,
             const float* __restrict__ bias,
             const float* __restrict__ Sv,
             const float* __restrict__ resid, long sR)
{
    extern __shared__ float smem[];
    const int ASZ = TRANSA ? TBK * APADT : TBM * APADN;
    const int BSZ = TBK * BPAD;
    const int BUF = ASZ + BSZ;

    const int b = blockIdx.z;
    A  += (long)b * sA;
    Bm += (long)b * sB;
    Cm += (long)b * sC;

    const int m0 = blockIdx.y * TBM;
    const int n0 = blockIdx.x * TBN;
    const int t  = threadIdx.x;
    const int lane = t & 31;
    const int w = t >> 5;
    const int wm = (w >> 1) * 32;    // 4 m-positions
    const int wn = (w & 1) * 64;     // 2 n-positions
    const int gid = lane >> 2;
    const int tig = lane & 3;

    float acc[2][8][4];
#pragma unroll
    for (int mt = 0; mt < 2; mt++)
#pragma unroll
        for (int nt = 0; nt < 8; nt++)
#pragma unroll
            for (int r = 0; r < 4; r++) acc[mt][nt][r] = 0.f;

    auto stage = [&](int kt, int buf) {
        float* as = smem + buf * BUF;
        float* bs = as + ASZ;
        const int k0 = kt * TBK;
        if (!TRANSA) {
#pragma unroll
            for (int i = 0; i < 4; i++) {
                int idx = t + i * 256;
                int m = idx >> 3, ch = idx & 7;
                const float* src = A + (long)(m0 + m) * K + k0 + ch * 4;
                CP16(su(as + m * APADN + ch * 4), src, 16);
            }
        } else {
#pragma unroll
            for (int i = 0; i < 4; i++) {
                int idx = t + i * 256;
                int kk = idx >> 5, m4 = idx & 31;
                const float* src = A + (long)(k0 + kk) * M + m0 + m4 * 4;
                unsigned sz = (m0 + m4 * 4 < M) ? 16u : 0u;
                CP16(su(as + kk * APADT + m4 * 4), src, sz);
            }
        }
#pragma unroll
        for (int i = 0; i < 4; i++) {
            int idx = t + i * 256;
            int kk = idx >> 5, n4 = idx & 31;
            const float* src = Bm + (long)(k0 + kk) * LN + n0 + n4 * 4;
            unsigned sz = (n0 + n4 * 4 < LN) ? 16u : 0u;
            CP16(su(bs + kk * BPAD + n4 * 4), src, sz);
        }
        asm volatile("cp.async.commit_group;");
    };

    const int nk = K / TBK;
    stage(0, 0);
    stage(1, 1);

    for (int it = 0; it < nk; it++) {
        if (it + 1 < nk)
            asm volatile("cp.async.wait_group 1;");
        else
            asm volatile("cp.async.wait_group 0;");
        __syncthreads();

        const float* as = smem + (it % 3) * BUF;
        const float* bs = as + ASZ;

#pragma unroll
        for (int ks = 0; ks < TBK / 8; ks++) {
            const int k = ks * 8;
            unsigned af[2][4], bf[8][2];
#pragma unroll
            for (int mt = 0; mt < 2; mt++) {
                int mrow = wm + mt * 16 + gid;
#pragma unroll
                for (int r = 0; r < 4; r++) {
                    int mr = mrow + (r & 1) * 8;
                    int kc = k + tig + (r >> 1) * 4;
                    float v = TRANSA ? as[kc * APADT + mr]
                                     : as[mr * APADN + kc];
                    af[mt][r] = __float_as_uint(v);
                }
            }
#pragma unroll
            for (int nt = 0; nt < 8; nt++) {
                int nc = wn + nt * 8 + gid;
#pragma unroll
                for (int r = 0; r < 2; r++)
                    bf[nt][r] = __float_as_uint(bs[(k + tig + r * 4) * BPAD + nc]);
            }
#pragma unroll
            for (int mt = 0; mt < 2; mt++)
#pragma unroll
                for (int nt = 0; nt < 8; nt++)
                    asm volatile(
                        "mma.sync.aligned.m16n8k8.row.col.f32.tf32.tf32.f32 "
                        "{%0,%1,%2,%3},{%4,%5,%6,%7},{%8,%9},{%0,%1,%2,%3};"
                        : "+f"(acc[mt][nt][0]), "+f"(acc[mt][nt][1]),
                          "+f"(acc[mt][nt][2]), "+f"(acc[mt][nt][3])
                        : "r"(af[mt][0]), "r"(af[mt][1]),
                          "r"(af[mt][2]), "r"(af[mt][3]),
                          "r"(bf[nt][0]), "r"(bf[nt][1]));
        }
        if (it + 2 < nk) stage(it + 2, (it + 2) % 3);
    }

    // ---- epilogue ----
#pragma unroll
    for (int mt = 0; mt < 2; mt++) {
#pragma unroll
        for (int nt = 0; nt < 8; nt++) {
#pragma unroll
            for (int r = 0; r < 4; r++) {
                int row = m0 + wm + mt * 16 + gid + (r >> 1) * 8;
                int col = n0 + wn + nt * 8 + tig * 2 + (r & 1);
                if (row < M && col < LN) {
                    float v = acc[mt][nt][r];
                    if (MODE == 0) v = rna_tf32(v + bias[row]);
                    if (MODE == 2)
                        v = (v + bias[row]) * Sv[b * LN + col]
                            + resid[(long)b * sR + (long)row * LN + col];
                    Cm[(long)row * LN + col] = v;
                }
            }
        }
    }
}

// ---------------- round-copy (f32 -> tf32-rounded f32) -----------------------
__global__ void roundcopy_kernel(const float* __restrict__ src,
                                 float* __restrict__ dst, long n4)
{
    long i = (long)blockIdx.x * blockDim.x + threadIdx.x;
    if (i >= n4) return;
    float4 v = ((const float4*)src)[i];
    v.x = rna_tf32(v.x); v.y = rna_tf32(v.y);
    v.z = rna_tf32(v.z); v.w = rna_tf32(v.w);
    ((float4*)dst)[i] = v;
}

// ---------------- pixel squared norms ---------------------------------------
__global__ void pixnorm_kernel()
{
    const int b = blockIdx.y;
    const int which = blockIdx.z;   // 0 = k, 1 = q
    const int tid = threadIdx.x;
    const int lane = tid & 31;
    const int cs = tid >> 5;
    const int l = blockIdx.x * 32 + lane;
    const float* src = which ? (g_q + (long)b * 2 * CN * LN)
                             : (g_k + (long)b * CN * LN);
    float s = 0.f;
    for (int c = cs; c < CN; c += 8) {
        float v = src[(long)c * LN + l];
        s += v * v;
    }
    __shared__ float red[256];
    red[tid] = s;
    __syncthreads();
    for (int off = 128; off >= 32; off >>= 1) {
        if (tid < off) red[tid] += red[tid + off];
        __syncthreads();
    }
    if (tid < 32) g_n2[which * BN * LN + b * LN + l] = red[tid];
}

// ---------------- patch norms ------------------------------------------------
__global__ void patchnorm_kernel()
{
    int idx = blockIdx.x * blockDim.x + threadIdx.x;
    if (idx >= 2 * BN * LN) return;
    int which = idx / (BN * LN);
    int rem = idx % (BN * LN);
    int b = rem / LN;
    int l = rem % LN;
    int li = l / WN, lj = l % WN;
    const float* n2 = g_n2 + which * BN * LN + b * LN;
    float s = 0.f;
#pragma unroll
    for (int di = -1; di <= 1; di++)
#pragma unroll
        for (int dj = -1; dj <= 1; dj++) {
            int i2 = li + di, j2 = lj + dj;
            if (i2 >= 0 && i2 < HN && j2 >= 0 && j2 < WN)
                s += n2[i2 * WN + j2];
        }
    g_pn[idx] = fmaxf(sqrtf(s), 1e-12f);
}

// ---------------- R + argmax over ref positions ------------------------------
__global__ void rstar_kernel()
{
    const int m = blockIdx.x;
    const int b = blockIdx.y;
    const int mi = m / WN, mj = m % WN;
    const float* G = g_gram + (long)b * LN * LN;
    const float* pnk = g_pn + b * LN;
    const int tid = threadIdx.x;

    float best = -1e30f;
    int barg = 0;
    for (int l = tid; l < LN; l += 128) {
        int li = l / WN, lj = l % WN;
        float s = 0.f;
#pragma unroll
        for (int di = -1; di <= 1; di++)
#pragma unroll
            for (int dj = -1; dj <= 1; dj++) {
                int li2 = li + di, lj2 = lj + dj;
                int mi2 = mi + di, mj2 = mj + dj;
                if (li2 >= 0 && li2 < HN && lj2 >= 0 && lj2 < WN &&
                    mi2 >= 0 && mi2 < HN && mj2 >= 0 && mj2 < WN) {
                    int off = di * WN + dj;
                    s += G[(long)(l + off) * LN + (m + off)];
                }
            }
        float v = s / pnk[l];
        if (v > best) { best = v; barg = l; }
    }
    __shared__ float sv[128];
    __shared__ int si[128];
    sv[tid] = best; si[tid] = barg;
    __syncthreads();
    for (int off = 64; off >= 1; off >>= 1) {
        if (tid < off) {
            if (sv[tid + off] > sv[tid] ||
                (sv[tid + off] == sv[tid] && si[tid + off] < si[tid])) {
                sv[tid] = sv[tid + off];
                si[tid] = si[tid + off];
            }
        }
        __syncthreads();
    }
    if (tid == 0) {
        g_rstar[b * LN + m] = sv[0] / g_pn[BN * LN + b * LN + m];
        g_arg[b * LN + m] = si[0];
    }
}

// ---------------- gather-index precompute ------------------------------------
__global__ void idx_kernel()
{
    int idx = blockIdx.x * blockDim.x + threadIdx.x;
    if (idx >= BN * LN) return;
    int b = idx / LN;
    int p = idx % LN;
    int pi = p / WN, pj = p % WN;
#pragma unroll
    for (int j = 0; j < 9; j++) {
        int di = j / 3 - 1, dj = j % 3 - 1;
        int mi = pi - di, mj = pj - dj;
        int id = -1;
        if (mi >= 0 && mi < HN && mj >= 0 && mj < WN) {
            int a = g_arg[b * LN + mi * WN + mj];
            int ai = a / WN + di, aj = a % WN + dj;
            if (ai >= 0 && ai < HN && aj >= 0 && aj < WN)
                id = ai * WN + aj;
        }
        g_idx[(long)(b * LN + p) * 9 + j] = id;
    }
}

// ---------------- build T_part (tf32-rounded) into second half of g_q --------
__global__ void tpart_kernel()
{
    const int c = blockIdx.x;
    const int b = blockIdx.y;
    const float* krow = g_k + ((long)b * CN + c) * LN;
    const int* idxr = g_idx + (long)b * LN * 9;
    const int p = threadIdx.x;
    float s = 0.f;
#pragma unroll
    for (int j = 0; j < 9; j++) {
        int id = idxr[p * 9 + j];
        if (id >= 0) s += krow[id];
    }
    g_q[((long)b * 2 * CN + CN + c) * LN + p] = rna_tf32(s * (1.f / 9.f));
}

// ---------------- host launch ------------------------------------------------
extern "C" void kernel_launch(void* const* d_in, const int* in_sizes, int n_in,
                              void* d_out, int out_size)
{
    const float* part_ref    = (const float*)d_in[0];
    const float* part_target = (const float*)d_in[1];
    const float* wq = (const float*)d_in[2];
    const float* bq = (const float*)d_in[3];
    const float* wk = (const float*)d_in[4];
    const float* bk = (const float*)d_in[5];
    const float* wt = (const float*)d_in[6];
    const float* bt = (const float*)d_in[7];
    float* out = (float*)d_out;

    float *q_ptr, *k_ptr, *pt_r, *pr_r, *wq_r, *wk_r, *wt_r, *g_ptr, *s_ptr;
    cudaGetSymbolAddress((void**)&q_ptr, g_q);
    cudaGetSymbolAddress((void**)&k_ptr, g_k);
    cudaGetSymbolAddress((void**)&pt_r,  g_pt);
    cudaGetSymbolAddress((void**)&pr_r,  g_pr);
    cudaGetSymbolAddress((void**)&wq_r,  g_wq);
    cudaGetSymbolAddress((void**)&wk_r,  g_wk);
    cudaGetSymbolAddress((void**)&wt_r,  g_wt);
    cudaGetSymbolAddress((void**)&g_ptr, g_gram);
    cudaGetSymbolAddress((void**)&s_ptr, g_rstar);

    // dynamic smem (3-stage)
    const int smemN = 3 * (TBM * APADN + TBK * BPAD) * 4;  // 107520
    const int smemT = 3 * (TBK * APADT + TBK * BPAD) * 4;  // 104448
    cudaFuncSetAttribute(gemm_tc<false, 0>,
        cudaFuncAttributeMaxDynamicSharedMemorySize, smemN);
    cudaFuncSetAttribute(gemm_tc<true, 1>,
        cudaFuncAttributeMaxDynamicSharedMemorySize, smemT);
    cudaFuncSetAttribute(gemm_tc<false, 2>,
        cudaFuncAttributeMaxDynamicSharedMemorySize, smemN);

    // 0) round all GEMM operands to tf32
    {
        long n4q = (long)CN * CN / 4;
        roundcopy_kernel<<<(int)((n4q + 255) / 256), 256>>>(wq, wq_r, n4q);
        roundcopy_kernel<<<(int)((n4q + 255) / 256), 256>>>(wk, wk_r, n4q);
        long n4t = (long)CN * 2 * CN / 4;
        roundcopy_kernel<<<(int)((n4t + 255) / 256), 256>>>(wt, wt_r, n4t);
        long n4f = (long)BN * CN * LN / 4;
        roundcopy_kernel<<<(int)((n4f + 255) / 256), 256>>>(part_target, pt_r, n4f);
        roundcopy_kernel<<<(int)((n4f + 255) / 256), 256>>>(part_ref, pr_r, n4f);
    }

    dim3 blk(256);
    const int NXT = (LN + TBN - 1) / TBN;   // 5

    // 1) q = rna(wq @ part_target + bq)   -> g_q rows [0,C)
    gemm_tc<false, 0><<<dim3(NXT, CN / TBM, BN), blk, smemN>>>(
        wq_r, pt_r, q_ptr, CN, CN,
        0L, (long)CN * LN, (long)2 * CN * LN, bq, nullptr, nullptr, 0L);

    // 2) k = rna(wk @ part_ref + bk)      -> g_k
    gemm_tc<false, 0><<<dim3(NXT, CN / TBM, BN), blk, smemN>>>(
        wk_r, pr_r, k_ptr, CN, CN,
        0L, (long)CN * LN, (long)CN * LN, bk, nullptr, nullptr, 0L);

    // 3) pixel squared norms
    pixnorm_kernel<<<dim3(LN / 32, BN, 2), 256>>>();
    // 4) patch norms
    patchnorm_kernel<<<(2 * BN * LN + 255) / 256, 256>>>();

    // 5) Gram: G[l,m] = sum_c k[c,l] q[c,m]
    gemm_tc<true, 1><<<dim3(NXT, (LN + TBM - 1) / TBM, BN), blk, smemT>>>(
        k_ptr, q_ptr, g_ptr, LN, CN,
        (long)CN * LN, (long)2 * CN * LN, (long)LN * LN,
        nullptr, nullptr, nullptr, 0L);

    // 6) R_star + argmax
    rstar_kernel<<<dim3(LN, BN), 128>>>();
    // 7) gather indices
    idx_kernel<<<(BN * LN + 255) / 256, 256>>>();
    // 8) T_part -> g_q rows [C,2C)
    tpart_kernel<<<dim3(CN, BN), LN>>>();

    // 9) final: out = (wt @ [q;T_part] + bt) * S + part_target
    gemm_tc<false, 2><<<dim3(NXT, CN / TBM, BN), blk, smemN>>>(
        wt_r, q_ptr, out, CN, 2 * CN,
        0L, (long)2 * CN * LN, (long)CN * LN, bt, s_ptr, part_target,
        (long)CN * LN);
}

// round 8
// speedup vs baseline: 5.0227x; 1.7117x over previous
#include <cuda_runtime.h>
#include <cuda_fp16.h>
#include <cstdint>

// Problem constants
#define BN 4
#define CN 2048
#define HN 24
#define WN 24
#define LN 576   // H*W

// GEMM tile constants
#define TBM 128
#define TBN 128
#define TBK 32
#define AROW  40    // !TRANSA A smem row stride in halves (80B = 5x16B, odd phase)
#define ATROW 136   // TRANSA  A smem row stride in halves (272B = 17x16B)
#define BROW  136   // B smem row stride in halves

// ---------------- scratch (device globals; no allocation allowed) -----------
__device__ __half g_q[(long)BN * 2 * CN * LN];  // [B][2C][L]: rows 0..C-1 = q, C..2C-1 = T_part
__device__ __half g_k[(long)BN * CN * LN];      // [B][C][L]
__device__ __half g_pt[(long)BN * CN * LN];     // part_target (half)
__device__ __half g_pr[(long)BN * CN * LN];     // part_ref (half)
__device__ __half g_wq[(long)CN * CN];
__device__ __half g_wk[(long)CN * CN];
__device__ __half g_wt[(long)CN * 2 * CN];
__device__ float g_gram[(long)BN * LN * LN];    // [B][L_ref][L_tgt]
__device__ float g_n2[2 * BN * LN];
__device__ float g_pn[2 * BN * LN];
__device__ float g_rstar[BN * LN];
__device__ int   g_arg[BN * LN];
__device__ int   g_idx[BN * LN * 9];

__device__ __forceinline__ unsigned su(const void* p) {
    return (unsigned)__cvta_generic_to_shared(p);
}
#define CP16(d, s, sz) \
    asm volatile("cp.async.cg.shared.global [%0], [%1], 16, %2;" \
                 :: "r"(d), "l"(s), "r"(sz))

__device__ __forceinline__ void ldm_x4(uint32_t* r, unsigned a) {
    asm volatile("ldmatrix.sync.aligned.m8n8.x4.shared.b16 {%0,%1,%2,%3}, [%4];"
                 : "=r"(r[0]), "=r"(r[1]), "=r"(r[2]), "=r"(r[3]) : "r"(a));
}
__device__ __forceinline__ void ldm_x4_t(uint32_t* r, unsigned a) {
    asm volatile("ldmatrix.sync.aligned.m8n8.x4.trans.shared.b16 {%0,%1,%2,%3}, [%4];"
                 : "=r"(r[0]), "=r"(r[1]), "=r"(r[2]), "=r"(r[3]) : "r"(a));
}
#define MMA16(d, a, b0, b1) \
    asm volatile( \
        "mma.sync.aligned.m16n8k16.row.col.f32.f16.f16.f32 " \
        "{%0,%1,%2,%3},{%4,%5,%6,%7},{%8,%9},{%0,%1,%2,%3};" \
        : "+f"((d)[0]), "+f"((d)[1]), "+f"((d)[2]), "+f"((d)[3]) \
        : "r"((a)[0]), "r"((a)[1]), "r"((a)[2]), "r"((a)[3]), \
          "r"(b0), "r"(b1))

// ---------------- fp16 tensor-core GEMM (mma.sync m16n8k16) ------------------
// C[M, LN] = op(A)[M,K] * B[K,LN] (half operands, f32 accumulate).
// op(A)=A row-major [M,K] if !TRANSA, else A stored [K,M] row-major.
// B row-major [K,LN]. K % 32 == 0.
// MODE 0: out(half) = half(acc + bias[row])
// MODE 1: out(f32)  = acc
// MODE 2: out(f32)  = (acc + bias[row]) * Sv[b*LN+col] + resid[b*sR + row*LN + col]
template<bool TRANSA, int MODE>
__global__ __launch_bounds__(256)
void gemm_h(const __half* __restrict__ A, const __half* __restrict__ Bm,
            void* __restrict__ Cm_, int M, int K,
            long sA, long sB, long sC,
            const float* __restrict__ bias,
            const float* __restrict__ Sv,
            const float* __restrict__ resid, long sR)
{
    extern __shared__ __half smem[];
    const int ASZ = TRANSA ? TBK * ATROW : TBM * AROW;
    const int BSZ = TBK * BROW;
    const int BUF = ASZ + BSZ;

    const int b = blockIdx.z;
    A  += (long)b * sA;
    Bm += (long)b * sB;

    const int m0 = blockIdx.y * TBM;
    const int n0 = blockIdx.x * TBN;
    const int t  = threadIdx.x;
    const int lane = t & 31;
    const int w = t >> 5;
    const int wm = (w >> 1) * 32;
    const int wn = (w & 1) * 64;
    const int gid = lane >> 2;
    const int tig = lane & 3;

    float acc[2][8][4];
#pragma unroll
    for (int mt = 0; mt < 2; mt++)
#pragma unroll
        for (int nt = 0; nt < 8; nt++)
#pragma unroll
            for (int r = 0; r < 4; r++) acc[mt][nt][r] = 0.f;

    auto stage = [&](int kt, int buf) {
        __half* as = smem + buf * BUF;
        __half* bs = as + ASZ;
        const int k0 = kt * TBK;
        if (!TRANSA) {
#pragma unroll
            for (int i = 0; i < 2; i++) {
                int idx = t + i * 256;
                int m = idx >> 2, ch = idx & 3;        // 4 chunks x 8 halves
                const __half* src = A + (long)(m0 + m) * K + k0 + ch * 8;
                unsigned sz = (m0 + m < M) ? 16u : 0u;
                CP16(su(as + m * AROW + ch * 8), src, sz);
            }
        } else {
#pragma unroll
            for (int i = 0; i < 2; i++) {
                int idx = t + i * 256;
                int kk = idx >> 4, ch = idx & 15;
                const __half* src = A + (long)(k0 + kk) * M + m0 + ch * 8;
                unsigned sz = (m0 + ch * 8 < M) ? 16u : 0u;
                CP16(su(as + kk * ATROW + ch * 8), src, sz);
            }
        }
#pragma unroll
        for (int i = 0; i < 2; i++) {
            int idx = t + i * 256;
            int kk = idx >> 4, ch = idx & 15;
            const __half* src = Bm + (long)(k0 + kk) * LN + n0 + ch * 8;
            unsigned sz = (n0 + ch * 8 < LN) ? 16u : 0u;
            CP16(su(bs + kk * BROW + ch * 8), src, sz);
        }
        asm volatile("cp.async.commit_group;");
    };

    const int nk = K / TBK;
    stage(0, 0);
    stage(1, 1);

    for (int it = 0; it < nk; it++) {
        if (it + 1 < nk)
            asm volatile("cp.async.wait_group 1;");
        else
            asm volatile("cp.async.wait_group 0;");
        __syncthreads();

        const __half* as = smem + (it % 3) * BUF;
        const __half* bs = as + ASZ;

#pragma unroll
        for (int ks = 0; ks < 2; ks++) {
            const int k = ks * 16;
            uint32_t af[2][4], bf[4][4];
            if (!TRANSA) {
#pragma unroll
                for (int mt = 0; mt < 2; mt++) {
                    unsigned a = su(as + (wm + mt * 16 + (lane & 15)) * AROW
                                       + k + (lane >> 4) * 8);
                    ldm_x4(af[mt], a);
                }
            } else {
#pragma unroll
                for (int mt = 0; mt < 2; mt++) {
                    unsigned a = su(as + (k + (lane & 7) + ((lane >> 4) & 1) * 8) * ATROW
                                       + wm + mt * 16 + ((lane >> 3) & 1) * 8);
                    ldm_x4_t(af[mt], a);
                }
            }
#pragma unroll
            for (int g = 0; g < 4; g++) {
                unsigned a = su(bs + (k + (lane & 7) + ((lane >> 3) & 1) * 8) * BROW
                                   + wn + g * 16 + ((lane >> 4) & 1) * 8);
                ldm_x4_t(bf[g], a);
            }
#pragma unroll
            for (int mt = 0; mt < 2; mt++)
#pragma unroll
                for (int nt = 0; nt < 8; nt++) {
                    int g = nt >> 1, h = (nt & 1) * 2;
                    MMA16(acc[mt][nt], af[mt], bf[g][h], bf[g][h + 1]);
                }
        }
        if (it + 2 < nk) stage(it + 2, (it + 2) % 3);
    }

    // ---- epilogue ----
#pragma unroll
    for (int mt = 0; mt < 2; mt++) {
#pragma unroll
        for (int rp = 0; rp < 2; rp++) {
            int row = m0 + wm + mt * 16 + gid + rp * 8;
            if (row >= M) continue;
            float bv = (MODE != 1) ? bias[row] : 0.f;
#pragma unroll
            for (int nt = 0; nt < 8; nt++) {
                int col = n0 + wn + nt * 8 + tig * 2;
                if (col >= LN) continue;
                float v0 = acc[mt][nt][rp * 2 + 0];
                float v1 = acc[mt][nt][rp * 2 + 1];
                if (MODE == 0) {
                    __half* C = (__half*)Cm_ + (long)b * sC;
                    *(__half2*)(C + (long)row * LN + col) =
                        __floats2half2_rn(v0 + bv, v1 + bv);
                } else if (MODE == 1) {
                    float* C = (float*)Cm_ + (long)b * sC;
                    *(float2*)(C + (long)row * LN + col) = make_float2(v0, v1);
                } else {
                    float* C = (float*)Cm_ + (long)b * sC;
                    const float* rs = resid + (long)b * sR + (long)row * LN + col;
                    float2 rv = *(const float2*)rs;
                    float2 o;
                    o.x = (v0 + bv) * Sv[b * LN + col + 0] + rv.x;
                    o.y = (v1 + bv) * Sv[b * LN + col + 1] + rv.y;
                    *(float2*)(C + (long)row * LN + col) = o;
                }
            }
        }
    }
}

// ---------------- f32 -> f16 conversion --------------------------------------
__global__ void tohalf_kernel(const float* __restrict__ src,
                              __half* __restrict__ dst, long n4)
{
    long i = (long)blockIdx.x * blockDim.x + threadIdx.x;
    if (i >= n4) return;
    float4 v = ((const float4*)src)[i];
    ((__half2*)dst)[i * 2 + 0] = __floats2half2_rn(v.x, v.y);
    ((__half2*)dst)[i * 2 + 1] = __floats2half2_rn(v.z, v.w);
}

// ---------------- pixel squared norms ---------------------------------------
__global__ void pixnorm_kernel()
{
    const int b = blockIdx.y;
    const int which = blockIdx.z;   // 0 = k, 1 = q
    const int tid = threadIdx.x;
    const int lane = tid & 31;
    const int cs = tid >> 5;
    const int l = blockIdx.x * 32 + lane;
    const __half* src = which ? (g_q + (long)b * 2 * CN * LN)
                              : (g_k + (long)b * CN * LN);
    float s = 0.f;
    for (int c = cs; c < CN; c += 8) {
        float v = __half2float(src[(long)c * LN + l]);
        s += v * v;
    }
    __shared__ float red[256];
    red[tid] = s;
    __syncthreads();
    for (int off = 128; off >= 32; off >>= 1) {
        if (tid < off) red[tid] += red[tid + off];
        __syncthreads();
    }
    if (tid < 32) g_n2[which * BN * LN + b * LN + l] = red[tid];
}

// ---------------- patch norms ------------------------------------------------
__global__ void patchnorm_kernel()
{
    int idx = blockIdx.x * blockDim.x + threadIdx.x;
    if (idx >= 2 * BN * LN) return;
    int which = idx / (BN * LN);
    int rem = idx % (BN * LN);
    int b = rem / LN;
    int l = rem % LN;
    int li = l / WN, lj = l % WN;
    const float* n2 = g_n2 + which * BN * LN + b * LN;
    float s = 0.f;
#pragma unroll
    for (int di = -1; di <= 1; di++)
#pragma unroll
        for (int dj = -1; dj <= 1; dj++) {
            int i2 = li + di, j2 = lj + dj;
            if (i2 >= 0 && i2 < HN && j2 >= 0 && j2 < WN)
                s += n2[i2 * WN + j2];
        }
    g_pn[idx] = fmaxf(sqrtf(s), 1e-12f);
}

// ---------------- R + argmax over ref positions ------------------------------
__global__ void rstar_kernel()
{
    const int m = blockIdx.x;
    const int b = blockIdx.y;
    const int mi = m / WN, mj = m % WN;
    const float* G = g_gram + (long)b * LN * LN;
    const float* pnk = g_pn + b * LN;
    const int tid = threadIdx.x;

    float best = -1e30f;
    int barg = 0;
    for (int l = tid; l < LN; l += 128) {
        int li = l / WN, lj = l % WN;
        float s = 0.f;
#pragma unroll
        for (int di = -1; di <= 1; di++)
#pragma unroll
            for (int dj = -1; dj <= 1; dj++) {
                int li2 = li + di, lj2 = lj + dj;
                int mi2 = mi + di, mj2 = mj + dj;
                if (li2 >= 0 && li2 < HN && lj2 >= 0 && lj2 < WN &&
                    mi2 >= 0 && mi2 < HN && mj2 >= 0 && mj2 < WN) {
                    int off = di * WN + dj;
                    s += G[(long)(l + off) * LN + (m + off)];
                }
            }
        float v = s / pnk[l];
        if (v > best) { best = v; barg = l; }
    }
    __shared__ float sv[128];
    __shared__ int si[128];
    sv[tid] = best; si[tid] = barg;
    __syncthreads();
    for (int off = 64; off >= 1; off >>= 1) {
        if (tid < off) {
            if (sv[tid + off] > sv[tid] ||
                (sv[tid + off] == sv[tid] && si[tid + off] < si[tid])) {
                sv[tid] = sv[tid + off];
                si[tid] = si[tid + off];
            }
        }
        __syncthreads();
    }
    if (tid == 0) {
        g_rstar[b * LN + m] = sv[0] / g_pn[BN * LN + b * LN + m];
        g_arg[b * LN + m] = si[0];
    }
}

// ---------------- gather-index precompute ------------------------------------
__global__ void idx_kernel()
{
    int idx = blockIdx.x * blockDim.x + threadIdx.x;
    if (idx >= BN * LN) return;
    int b = idx / LN;
    int p = idx % LN;
    int pi = p / WN, pj = p % WN;
#pragma unroll
    for (int j = 0; j < 9; j++) {
        int di = j / 3 - 1, dj = j % 3 - 1;
        int mi = pi - di, mj = pj - dj;
        int id = -1;
        if (mi >= 0 && mi < HN && mj >= 0 && mj < WN) {
            int a = g_arg[b * LN + mi * WN + mj];
            int ai = a / WN + di, aj = a % WN + dj;
            if (ai >= 0 && ai < HN && aj >= 0 && aj < WN)
                id = ai * WN + aj;
        }
        g_idx[(long)(b * LN + p) * 9 + j] = id;
    }
}

// ---------------- build T_part (half) into second half of g_q ----------------
__global__ void tpart_kernel()
{
    const int c = blockIdx.x;
    const int b = blockIdx.y;
    const __half* krow = g_k + ((long)b * CN + c) * LN;
    const int* idxr = g_idx + (long)b * LN * 9;
    const int p = threadIdx.x;
    float s = 0.f;
#pragma unroll
    for (int j = 0; j < 9; j++) {
        int id = idxr[p * 9 + j];
        if (id >= 0) s += __half2float(krow[id]);
    }
    g_q[((long)b * 2 * CN + CN + c) * LN + p] = __float2half_rn(s * (1.f / 9.f));
}

// ---------------- host launch ------------------------------------------------
extern "C" void kernel_launch(void* const* d_in, const int* in_sizes, int n_in,
                              void* d_out, int out_size)
{
    const float* part_ref    = (const float*)d_in[0];
    const float* part_target = (const float*)d_in[1];
    const float* wq = (const float*)d_in[2];
    const float* bq = (const float*)d_in[3];
    const float* wk = (const float*)d_in[4];
    const float* bk = (const float*)d_in[5];
    const float* wt = (const float*)d_in[6];
    const float* bt = (const float*)d_in[7];
    float* out = (float*)d_out;

    __half *q_ptr, *k_ptr, *pt_h, *pr_h, *wq_h, *wk_h, *wt_h;
    float *g_ptr, *s_ptr;
    cudaGetSymbolAddress((void**)&q_ptr, g_q);
    cudaGetSymbolAddress((void**)&k_ptr, g_k);
    cudaGetSymbolAddress((void**)&pt_h,  g_pt);
    cudaGetSymbolAddress((void**)&pr_h,  g_pr);
    cudaGetSymbolAddress((void**)&wq_h,  g_wq);
    cudaGetSymbolAddress((void**)&wk_h,  g_wk);
    cudaGetSymbolAddress((void**)&wt_h,  g_wt);
    cudaGetSymbolAddress((void**)&g_ptr, g_gram);
    cudaGetSymbolAddress((void**)&s_ptr, g_rstar);

    // dynamic smem (3-stage), in bytes
    const int smemN = 3 * (TBM * AROW + TBK * BROW) * 2;   // 56832
    const int smemT = 3 * (TBK * ATROW + TBK * BROW) * 2;  // 52224
    cudaFuncSetAttribute(gemm_h<false, 0>,
        cudaFuncAttributeMaxDynamicSharedMemorySize, smemN);
    cudaFuncSetAttribute(gemm_h<true, 1>,
        cudaFuncAttributeMaxDynamicSharedMemorySize, smemT);
    cudaFuncSetAttribute(gemm_h<false, 2>,
        cudaFuncAttributeMaxDynamicSharedMemorySize, smemN);

    // 0) convert all GEMM operands to half
    {
        long n4q = (long)CN * CN / 4;
        tohalf_kernel<<<(int)((n4q + 255) / 256), 256>>>(wq, wq_h, n4q);
        tohalf_kernel<<<(int)((n4q + 255) / 256), 256>>>(wk, wk_h, n4q);
        long n4t = (long)CN * 2 * CN / 4;
        tohalf_kernel<<<(int)((n4t + 255) / 256), 256>>>(wt, wt_h, n4t);
        long n4f = (long)BN * CN * LN / 4;
        tohalf_kernel<<<(int)((n4f + 255) / 256), 256>>>(part_target, pt_h, n4f);
        tohalf_kernel<<<(int)((n4f + 255) / 256), 256>>>(part_ref, pr_h, n4f);
    }

    dim3 blk(256);
    const int NXT = (LN + TBN - 1) / TBN;   // 5

    // 1) q = half(wq @ part_target + bq)   -> g_q rows [0,C)
    gemm_h<false, 0><<<dim3(NXT, CN / TBM, BN), blk, smemN>>>(
        wq_h, pt_h, q_ptr, CN, CN,
        0L, (long)CN * LN, (long)2 * CN * LN, bq, nullptr, nullptr, 0L);

    // 2) k = half(wk @ part_ref + bk)      -> g_k
    gemm_h<false, 0><<<dim3(NXT, CN / TBM, BN), blk, smemN>>>(
        wk_h, pr_h, k_ptr, CN, CN,
        0L, (long)CN * LN, (long)CN * LN, bk, nullptr, nullptr, 0L);

    // 3) pixel squared norms
    pixnorm_kernel<<<dim3(LN / 32, BN, 2), 256>>>();
    // 4) patch norms
    patchnorm_kernel<<<(2 * BN * LN + 255) / 256, 256>>>();

    // 5) Gram: G[l,m] = sum_c k[c,l] q[c,m]   (f32 out)
    gemm_h<true, 1><<<dim3(NXT, (LN + TBM - 1) / TBM, BN), blk, smemT>>>(
        k_ptr, q_ptr, g_ptr, LN, CN,
        (long)CN * LN, (long)2 * CN * LN, (long)LN * LN,
        nullptr, nullptr, nullptr, 0L);

    // 6) R_star + argmax
    rstar_kernel<<<dim3(LN, BN), 128>>>();
    // 7) gather indices
    idx_kernel<<<(BN * LN + 255) / 256, 256>>>();
    // 8) T_part -> g_q rows [C,2C)
    tpart_kernel<<<dim3(CN, BN), LN>>>();

    // 9) final: out = (wt @ [q;T_part] + bt) * S + part_target
    gemm_h<false, 2><<<dim3(NXT, CN / TBM, BN), blk, smemN>>>(
        wt_h, q_ptr, out, CN, 2 * CN,
        0L, (long)2 * CN * LN, (long)CN * LN, bt, s_ptr, part_target,
        (long)CN * LN);
}